// round 17
// baseline (speedup 1.0000x reference)
#include <cuda_runtime.h>
#include <cstdint>

#define B_DIM 2048
#define I_DIM 512
#define O_DIM 512

#define BM 128
#define BN 64
#define BK 8
#define NTH 128
#define KSPLIT 8
#define KLEN (I_DIM / KSPLIT)   // 64
#define OUTN (B_DIM * O_DIM)    // 1048576

// g_AB[k][o] = {a, a, b, b}  (interleaved + duplicated): 512*512*4 floats = 4 MB
__device__ float g_AB[I_DIM * O_DIM * 4];
// 7 partial-product planes
__device__ float g_P[(KSPLIT - 1) * OUTN];

// ---------- packed f32x2 helpers ----------
__device__ __forceinline__ unsigned long long pack2(float lo, float hi) {
    unsigned long long r;
    asm("mov.b64 %0, {%1, %2};" : "=l"(r) : "f"(lo), "f"(hi));
    return r;
}
__device__ __forceinline__ void unpack2(unsigned long long v, float& lo, float& hi) {
    asm("mov.b64 {%0, %1}, %2;" : "=f"(lo), "=f"(hi) : "l"(v));
}
__device__ __forceinline__ unsigned long long fma2(unsigned long long a, unsigned long long b,
                                                   unsigned long long c) {
    unsigned long long d;
    asm("fma.rn.f32x2 %0, %1, %2, %3;" : "=l"(d) : "l"(a), "l"(b), "l"(c));
    return d;
}
__device__ __forceinline__ unsigned long long mul2(unsigned long long a, unsigned long long b) {
    unsigned long long d;
    asm("mul.rn.f32x2 %0, %1, %2;" : "=l"(d) : "l"(a), "l"(b));
    return d;
}

// ---------- cp.async helpers ----------
__device__ __forceinline__ void cp_async16(uint32_t smem_addr, const void* gptr) {
    asm volatile("cp.async.cg.shared.global [%0], [%1], 16;" :: "r"(smem_addr), "l"(gptr));
}
__device__ __forceinline__ void cp_commit() { asm volatile("cp.async.commit_group;"); }
__device__ __forceinline__ void cp_wait0()  { asm volatile("cp.async.wait_group 0;"); }

// ---------- prep: sigmoid + refactor -> interleaved dup'd {a,a,b,b} ----------
__global__ void prep_kernel(const float* __restrict__ wl, const float* __restrict__ sl) {
    int idx = blockIdx.x * blockDim.x + threadIdx.x;   // (k, o) flat, 0..262143
    float w = 1.0f / (1.0f + __expf(-wl[idx]));
    float s = 1.0f / (1.0f + __expf(-sl[idx]));
    float a = 1.0f - w * s;             // factor = a + x*b
    float b = w * (2.0f * s - 1.0f);
    ((float4*)g_AB)[idx] = make_float4(a, a, b, b);
}

// ---------- combine: OUT *= product of 7 partial planes ----------
__global__ void combine_kernel(float* __restrict__ OUT) {
    int i = blockIdx.x * blockDim.x + threadIdx.x;   // float4 index
    float4 o = ((const float4*)OUT)[i];
#pragma unroll
    for (int s = 0; s < KSPLIT - 1; s++) {
        float4 p = ((const float4*)(g_P + s * OUTN))[i];
        o.x *= p.x; o.y *= p.y; o.z *= p.z; o.w *= p.w;
    }
    ((float4*)OUT)[i] = o;
}

// ---------- main: product-GEMM, 128x64 tile, 16x4 microtile, k-split x8 ----------
__global__ __launch_bounds__(NTH)
void fuzzy_prod_kernel(const float* __restrict__ X, float* __restrict__ OUT) {
    __shared__ __align__(16) float Xs[2][BK][BM];        // 8 KB
    __shared__ __align__(16) float ABs[2][BK * BN * 4];  // 16 KB

    const int tid = threadIdx.x;
    const int tx  = tid & 15;      // o-quad: o = 4tx .. 4tx+3
    const int ty  = tid >> 4;      // b-group: rows ty*16 .. ty*16+15 (8 groups)
    const int bn0 = blockIdx.x * BN;
    const int bm0 = blockIdx.y * BM;
    const int k0  = blockIdx.z * KLEN;
    float* dst = (blockIdx.z == 0) ? OUT : (g_P + (blockIdx.z - 1) * OUTN);

    // X loader: 128 rows x 8 k -> 2 float4 per thread (one row each)
    const float* gX = &X[(bm0 + tid) * I_DIM + k0];
    // AB loader: tile = BK rows x 64 o x 4 floats = 2048 floats = 512 x 16B chunks,
    //   4 chunks/thread: chunk ci = tid + j*128; k = ci>>6, o = ci&63
    const float* gAB = &g_AB[k0 * (O_DIM * 4) + bn0 * 4];
    const uint32_t sAB0 = (uint32_t)__cvta_generic_to_shared(&ABs[0][0]);
    const uint32_t bufBytesAB = (uint32_t)(BK * BN * 4 * sizeof(float));

    const unsigned long long ONE2 = pack2(1.0f, 1.0f);
    // acc[p][j]: packed b-pair (ty*16+2p, ty*16+2p+1), o column 4tx+j
    unsigned long long acc[8][4];
#pragma unroll
    for (int p = 0; p < 8; p++)
#pragma unroll
        for (int j = 0; j < 4; j++) acc[p][j] = ONE2;

    // ---- prologue: fill buffer 0 ----
    {
#pragma unroll
        for (int j = 0; j < 4; j++) {
            int ci = tid + j * NTH;           // 0..511
            int kk = ci >> 6, oo = ci & 63;
            cp_async16(sAB0 + (uint32_t)(ci * 16),
                       gAB + kk * (O_DIM * 4) + oo * 4);
        }
        cp_commit();
        float4 x0 = *(const float4*)&gX[0];
        float4 x1 = *(const float4*)&gX[4];
        float xv[8] = {x0.x, x0.y, x0.z, x0.w, x1.x, x1.y, x1.z, x1.w};
#pragma unroll
        for (int j = 0; j < 8; j++) Xs[0][j][tid] = xv[j];   // 1 wf per STS
        cp_wait0();
    }
    __syncthreads();

    int buf = 0;
    for (int kt = 0; kt < KLEN; kt += BK) {
        const int nxt = buf ^ 1;
        const bool has_next = (kt + BK < KLEN);
        float4 x0, x1;
        if (has_next) {
            const uint32_t soff = (nxt ? bufBytesAB : 0);
            const float* gABn = gAB + (kt + BK) * (O_DIM * 4);
#pragma unroll
            for (int j = 0; j < 4; j++) {
                int ci = tid + j * NTH;
                int kk = ci >> 6, oo = ci & 63;
                cp_async16(sAB0 + soff + (uint32_t)(ci * 16),
                           gABn + kk * (O_DIM * 4) + oo * 4);
            }
            cp_commit();
            x0 = *(const float4*)&gX[kt + BK];
            x1 = *(const float4*)&gX[kt + BK + 4];
        }

#pragma unroll
        for (int k = 0; k < BK; k++) {
            // X: 4 broadcast LDS.128 -> 8 packed b-pairs, packs free
            unsigned long long xp[8];
#pragma unroll
            for (int c = 0; c < 4; c++) {
                float4 xq = *(const float4*)&Xs[buf][k][ty * 16 + 4 * c];
                xp[2 * c]     = pack2(xq.x, xq.y);
                xp[2 * c + 1] = pack2(xq.z, xq.w);
            }
            // AB: 4 LDS.128, each = {a,a,b,b} for one o column; dups free
#pragma unroll
            for (int j = 0; j < 4; j++) {
                float4 ab = *(const float4*)&ABs[buf][k * (BN * 4) + (tx * 4 + j) * 4];
                unsigned long long ad = pack2(ab.x, ab.y);
                unsigned long long bd = pack2(ab.z, ab.w);
#pragma unroll
                for (int p = 0; p < 8; p++)
                    acc[p][j] = mul2(acc[p][j], fma2(xp[p], bd, ad));
            }
        }

        if (has_next) {
            float xv[8] = {x0.x, x0.y, x0.z, x0.w, x1.x, x1.y, x1.z, x1.w};
#pragma unroll
            for (int j = 0; j < 8; j++) Xs[nxt][j][tid] = xv[j];
            cp_wait0();
        }
        __syncthreads();
        buf = nxt;
    }

    // ---- epilogue: 16 coalesced STG.128 per thread ----
#pragma unroll
    for (int p = 0; p < 8; p++) {
        float4 r0, r1;
        unpack2(acc[p][0], r0.x, r1.x);
        unpack2(acc[p][1], r0.y, r1.y);
        unpack2(acc[p][2], r0.z, r1.z);
        unpack2(acc[p][3], r0.w, r1.w);
        const int row = bm0 + ty * 16 + 2 * p;
        *(float4*)&dst[row * O_DIM + bn0 + tx * 4]       = r0;
        *(float4*)&dst[(row + 1) * O_DIM + bn0 + tx * 4] = r1;
    }
}

extern "C" void kernel_launch(void* const* d_in, const int* in_sizes, int n_in,
                              void* d_out, int out_size) {
    const float* x  = (const float*)d_in[0];   // (2048, 512)
    const float* wl = (const float*)d_in[1];   // (512, 512)
    const float* sl = (const float*)d_in[2];   // (512, 512)
    float* out = (float*)d_out;                // (2048, 512)

    prep_kernel<<<(I_DIM * O_DIM) / 256, 256>>>(wl, sl);

    dim3 grid(O_DIM / BN, B_DIM / BM, KSPLIT);  // (8, 16, 8) = 1024 CTAs
    fuzzy_prod_kernel<<<grid, NTH>>>(x, out);

    combine_kernel<<<(OUTN / 4) / 256, 256>>>(out);
}